// round 11
// baseline (speedup 1.0000x reference)
#include <cuda_runtime.h>
#include <cuda_bf16.h>

// Problem: out[r] = prod_{k=0..2} sigmoid((ub[k]-logit(bins[idx[r][k]]))/(ub[k]-lb[k]+1e-4))
// 1024 bins, 3 cols, 16.78M rows. Collapses to a 3x1024 LUT + streaming gather-product.
//
// R9: 4x-replicated LUT in 48KB *static* shared memory (no dynamic-smem
// attribute -> no per-launch reconfiguration tax), 512-thread blocks,
// 3 CTAs/SM (48 warps/SM). Lane-major int4 index loads + 2-deep pipeline +
// warp-carry row stitching, LUT built in-CTA.

#define N_BINS   1024
#define N_COLS   3
#define LUT_SIZE (N_BINS * N_COLS)
#define REP      4
#define REP_SH   2
#define LUT_REP_FLOATS (LUT_SIZE * REP)  // 12288 floats = 48KB

#define BLOCK_THREADS 512
#define WARPS_PER_BLOCK (BLOCK_THREADS / 32)

// ---------------------------------------------------------------------------
// Warp-carry product stitching round. Lane l of round j holds 4 consecutive
// ints whose columns are (mj, mj+1, mj+2, mj) mod 3. The lane holding a row's
// col-2 element completes the row; leading partials of the next row travel to
// lane+1 via shfl_up, and from lane 31 to lane 0 of the next round.
// Offsets o0/o1/o2 are pre-scaled by REP and carry the replica slot (lane&3).
// ---------------------------------------------------------------------------
__device__ __forceinline__ float do_round(int4 v, const float* __restrict__ lut,
                                          int o0, int o1, int o2, int mj,
                                          float qprev, float* __restrict__ out,
                                          unsigned g0, int lane)
{
    float w0 = lut[o0 + (v.x << REP_SH)];
    float w1 = lut[o1 + (v.y << REP_SH)];
    float w2 = lut[o2 + (v.z << REP_SH)];
    float w3 = lut[o0 + (v.w << REP_SH)];

    float m01 = w0 * w1;
    float w23 = w2 * w3;

    float q = (mj == 0) ? w3 : w23;
    float qin = __shfl_up_sync(0xffffffffu, q, 1);
    if (lane == 0) qin = qprev;

    float res;
    if (mj == 0)      res = m01 * w2;      // full row in-lane
    else if (mj == 1) res = qin * m01;     // qin = col0 from previous lane
    else              res = qin * w0;      // qin = col0*col1 from previous lane

    unsigned rA = g0 / 3u;
    out[rA] = res;
    if (mj == 2) out[rA + 1] = w1 * w23;   // this lane also holds a full row

    return __shfl_sync(0xffffffffu, q, 31);
}

__global__ void __launch_bounds__(BLOCK_THREADS, 3)
fused_kernel(const float* __restrict__ bin_centers,
             const int4* __restrict__ idx4,
             const float* __restrict__ lb,
             const float* __restrict__ ub,
             float* __restrict__ out, int nchunks)
{
    __shared__ float lut[LUT_REP_FLOATS];   // 48KB static, 4x-replicated

    // ---- Build the replicated LUT in-CTA (6 values per thread). ----
    for (int i = threadIdx.x; i < LUT_SIZE; i += BLOCK_THREADS) {
        int bin = i & (N_BINS - 1);
        int col = i >> 10;
        float c = bin_centers[bin];
        float logit = logf(c / (1.0f - c));
        float u = ub[col];
        float l = lb[col];
        float x = (u - logit) / (u - l + 1e-4f);
        float v = 1.0f / (1.0f + expf(-x));
        *(float4*)&lut[(size_t)i * REP] = make_float4(v, v, v, v);
    }
    __syncthreads();

    const int lane = threadIdx.x & 31;
    const int warpsTotal = gridDim.x * WARPS_PER_BLOCK;
    const int warpGlobal = blockIdx.x * WARPS_PER_BLOCK + (threadIdx.x >> 5);

    const int slot = lane & (REP - 1);     // replica slot 0..3
    const int m    = lane % 3;
    const int offA = (m * N_BINS << REP_SH) + slot;
    const int offB = ((((m + 1) % 3) * N_BINS) << REP_SH) + slot;
    const int offC = ((((m + 2) % 3) * N_BINS) << REP_SH) + slot;
    const int m0 = m;
    const int m1 = (m + 2) % 3;
    const int m2 = (m + 1) % 3;

    int c = warpGlobal;
    if (c >= nchunks) return;

    // 2-deep software pipeline on the index loads.
    int4 v0 = __ldcs(idx4 + c * 96 + lane);
    int4 v1 = __ldcs(idx4 + c * 96 + 32 + lane);
    int4 v2 = __ldcs(idx4 + c * 96 + 64 + lane);

    while (true) {
        int cn = c + warpsTotal;
        bool more = cn < nchunks;
        int4 n0, n1, n2;
        if (more) {
            n0 = __ldcs(idx4 + cn * 96 + lane);
            n1 = __ldcs(idx4 + cn * 96 + 32 + lane);
            n2 = __ldcs(idx4 + cn * 96 + 64 + lane);
        }

        unsigned Gw = (unsigned)c * 384u + 4u * (unsigned)lane;
        float qprev = 0.0f;
        qprev = do_round(v0, lut, offA, offB, offC, m0, qprev, out, Gw,        lane);
        qprev = do_round(v1, lut, offC, offA, offB, m1, qprev, out, Gw + 128u, lane);
        (void)  do_round(v2, lut, offB, offC, offA, m2, qprev, out, Gw + 256u, lane);

        if (!more) break;
        c = cn; v0 = n0; v1 = n1; v2 = n2;
    }
}

// ---------------------------------------------------------------------------
// Tail: per-row direct-compute path for rows not covered by full chunks
// (not hit for 16.78M rows; defensive only).
// ---------------------------------------------------------------------------
__global__ void tail_kernel(const float* __restrict__ bin_centers,
                            const int* __restrict__ idx,
                            const float* __restrict__ lb,
                            const float* __restrict__ ub,
                            float* __restrict__ out,
                            int start_row, int n_rows)
{
    int r = start_row + blockIdx.x * blockDim.x + threadIdx.x;
    if (r >= n_rows) return;
    float p = 1.0f;
#pragma unroll
    for (int k = 0; k < 3; k++) {
        float cb = bin_centers[idx[3 * r + k]];
        float logit = logf(cb / (1.0f - cb));
        float x = (ub[k] - logit) / (ub[k] - lb[k] + 1e-4f);
        p *= 1.0f / (1.0f + expf(-x));
    }
    out[r] = p;
}

extern "C" void kernel_launch(void* const* d_in, const int* in_sizes, int n_in,
                              void* d_out, int out_size)
{
    const float* bin_centers = (const float*)d_in[0];
    const int*   idx         = (const int*)d_in[1];
    const float* lb          = (const float*)d_in[2];
    const float* ub          = (const float*)d_in[3];
    float*       out         = (float*)d_out;

    int n_rows = in_sizes[1] / 3;
    int nchunks = n_rows / 128;   // 128 rows per warp-chunk

    if (nchunks > 0) {
        int blocks = 456;         // 3 CTAs/SM x 152 SMs = one wave
        if (blocks * WARPS_PER_BLOCK > nchunks)
            blocks = (nchunks + WARPS_PER_BLOCK - 1) / WARPS_PER_BLOCK;
        fused_kernel<<<blocks, BLOCK_THREADS>>>(
            bin_centers, (const int4*)idx, lb, ub, out, nchunks);
    }

    int done = nchunks * 128;
    if (done < n_rows) {
        int rem = n_rows - done;
        tail_kernel<<<(rem + 255) / 256, 256>>>(
            bin_centers, idx, lb, ub, out, done, n_rows);
    }
}

// round 12
// speedup vs baseline: 1.0461x; 1.0461x over previous
#include <cuda_runtime.h>
#include <cuda_bf16.h>

// Problem: out[r] = prod_{k=0..2} sigmoid((ub[k]-logit(bins[idx[r][k]]))/(ub[k]-lb[k]+1e-4))
// 1024 bins, 3 cols, 16.78M rows -> LUT + streaming gather-product.
//
// R11: input-adaptive LUT layout in 32KB *static* smem (no dynamic-smem
// per-replay tax), 512-thread blocks, 3 CTAs/SM (48 warps/SM).
//  - If lb/ub identical across columns (true for this dataset), the 3 column
//    tables coincide: ONE 1024-entry table replicated 8x. Bank = 8*(idx&3) +
//    (lane&7): cross-slot collisions impossible, degree ~2.1.
//  - Otherwise: 3 tables replicated 2x (correct, slower; not hit here).
// Unified gather: w = lut[v*MUL + OFF_col] with runtime MUL/OFF.
// Lane-major int4 index loads + 2-deep pipeline + warp-carry row stitching.

#define N_BINS   1024
#define LUT_FLOATS 8192      // 32KB

#define BLOCK_THREADS 512
#define WARPS_PER_BLOCK (BLOCK_THREADS / 32)

// ---------------------------------------------------------------------------
// Warp-carry product stitching round. Lane l of round j holds 4 consecutive
// ints whose columns are (mj, mj+1, mj+2, mj) mod 3. The lane holding a row's
// col-2 element completes the row; leading partials of the next row travel to
// lane+1 via shfl_up, and from lane 31 to lane 0 of the next round.
// ---------------------------------------------------------------------------
__device__ __forceinline__ float do_round(int4 v, const float* __restrict__ lut,
                                          int mul, int o0, int o1, int o2, int mj,
                                          float qprev, float* __restrict__ out,
                                          unsigned g0, int lane)
{
    float w0 = lut[v.x * mul + o0];
    float w1 = lut[v.y * mul + o1];
    float w2 = lut[v.z * mul + o2];
    float w3 = lut[v.w * mul + o0];

    float m01 = w0 * w1;
    float w23 = w2 * w3;

    float q = (mj == 0) ? w3 : w23;
    float qin = __shfl_up_sync(0xffffffffu, q, 1);
    if (lane == 0) qin = qprev;

    float res;
    if (mj == 0)      res = m01 * w2;      // full row in-lane
    else if (mj == 1) res = qin * m01;     // qin = col0 from previous lane
    else              res = qin * w0;      // qin = col0*col1 from previous lane

    unsigned rA = g0 / 3u;
    __stcs(&out[rA], res);
    if (mj == 2) __stcs(&out[rA + 1], w1 * w23);  // full row also in-lane

    return __shfl_sync(0xffffffffu, q, 31);
}

__device__ __forceinline__ float lut_value(float c, float u, float l) {
    float logit = logf(c / (1.0f - c));
    float x = (u - logit) / (u - l + 1e-4f);
    return 1.0f / (1.0f + expf(-x));
}

__global__ void __launch_bounds__(BLOCK_THREADS, 3)
fused_kernel(const float* __restrict__ bin_centers,
             const int4* __restrict__ idx4,
             const float* __restrict__ lb,
             const float* __restrict__ ub,
             float* __restrict__ out, int nchunks)
{
    __shared__ float lut[LUT_FLOATS];   // 32KB static

    const float l0 = lb[0], l1 = lb[1], l2 = lb[2];
    const float u0 = ub[0], u1 = ub[1], u2 = ub[2];
    const bool eq = (l0 == l1) && (l1 == l2) && (u0 == u1) && (u1 == u2);

    if (eq) {
        // Single table, REP=8: entry i occupies lut[8i .. 8i+7].
        for (int i = threadIdx.x; i < N_BINS; i += BLOCK_THREADS) {
            float v = lut_value(bin_centers[i], u0, l0);
            float4 v4 = make_float4(v, v, v, v);
            float4* dst = (float4*)&lut[i * 8];
            dst[0] = v4;
            dst[1] = v4;
        }
    } else {
        // Three tables, REP=2: table k at float offset k*2048.
        for (int i = threadIdx.x; i < 3 * N_BINS; i += BLOCK_THREADS) {
            int bin = i & (N_BINS - 1);
            int col = i >> 10;
            float u = (col == 0) ? u0 : (col == 1) ? u1 : u2;
            float l = (col == 0) ? l0 : (col == 1) ? l1 : l2;
            float v = lut_value(bin_centers[bin], u, l);
            *(float2*)&lut[i * 2] = make_float2(v, v);
        }
    }
    __syncthreads();

    const int lane = threadIdx.x & 31;
    const int warpsTotal = gridDim.x * WARPS_PER_BLOCK;
    const int warpGlobal = blockIdx.x * WARPS_PER_BLOCK + (threadIdx.x >> 5);

    // Runtime gather constants.
    int mul, t0, t1, t2;
    if (eq) {
        mul = 8;
        int slot = lane & 7;
        t0 = slot; t1 = slot; t2 = slot;
    } else {
        mul = 2;
        int slot = lane & 1;
        t0 = slot; t1 = 2048 + slot; t2 = 4096 + slot;
    }

    // Per-lane column rotation: lane's first element has column m = lane%3.
    const int m = lane % 3;
    const int offA = (m == 0) ? t0 : (m == 1) ? t1 : t2;
    const int offB = (m == 0) ? t1 : (m == 1) ? t2 : t0;
    const int offC = (m == 0) ? t2 : (m == 1) ? t0 : t1;
    const int m0 = m;
    const int m1 = (m + 2) % 3;
    const int m2 = (m + 1) % 3;

    int c = warpGlobal;
    if (c >= nchunks) return;

    // 2-deep software pipeline on the index loads.
    int4 v0 = __ldcs(idx4 + c * 96 + lane);
    int4 v1 = __ldcs(idx4 + c * 96 + 32 + lane);
    int4 v2 = __ldcs(idx4 + c * 96 + 64 + lane);

    while (true) {
        int cn = c + warpsTotal;
        bool more = cn < nchunks;
        int4 n0, n1, n2;
        if (more) {
            n0 = __ldcs(idx4 + cn * 96 + lane);
            n1 = __ldcs(idx4 + cn * 96 + 32 + lane);
            n2 = __ldcs(idx4 + cn * 96 + 64 + lane);
        }

        unsigned Gw = (unsigned)c * 384u + 4u * (unsigned)lane;
        float qprev = 0.0f;
        qprev = do_round(v0, lut, mul, offA, offB, offC, m0, qprev, out, Gw,        lane);
        qprev = do_round(v1, lut, mul, offC, offA, offB, m1, qprev, out, Gw + 128u, lane);
        (void)  do_round(v2, lut, mul, offB, offC, offA, m2, qprev, out, Gw + 256u, lane);

        if (!more) break;
        c = cn; v0 = n0; v1 = n1; v2 = n2;
    }
}

// ---------------------------------------------------------------------------
// Tail: per-row direct-compute path for rows not covered by full chunks
// (not hit for 16.78M rows; defensive only).
// ---------------------------------------------------------------------------
__global__ void tail_kernel(const float* __restrict__ bin_centers,
                            const int* __restrict__ idx,
                            const float* __restrict__ lb,
                            const float* __restrict__ ub,
                            float* __restrict__ out,
                            int start_row, int n_rows)
{
    int r = start_row + blockIdx.x * blockDim.x + threadIdx.x;
    if (r >= n_rows) return;
    float p = 1.0f;
#pragma unroll
    for (int k = 0; k < 3; k++) {
        float cb = bin_centers[idx[3 * r + k]];
        float logit = logf(cb / (1.0f - cb));
        float x = (ub[k] - logit) / (ub[k] - lb[k] + 1e-4f);
        p *= 1.0f / (1.0f + expf(-x));
    }
    out[r] = p;
}

extern "C" void kernel_launch(void* const* d_in, const int* in_sizes, int n_in,
                              void* d_out, int out_size)
{
    const float* bin_centers = (const float*)d_in[0];
    const int*   idx         = (const int*)d_in[1];
    const float* lb          = (const float*)d_in[2];
    const float* ub          = (const float*)d_in[3];
    float*       out         = (float*)d_out;

    int n_rows = in_sizes[1] / 3;
    int nchunks = n_rows / 128;   // 128 rows per warp-chunk

    if (nchunks > 0) {
        int blocks = 456;         // 3 CTAs/SM x 152 SMs = one wave
        if (blocks * WARPS_PER_BLOCK > nchunks)
            blocks = (nchunks + WARPS_PER_BLOCK - 1) / WARPS_PER_BLOCK;
        fused_kernel<<<blocks, BLOCK_THREADS>>>(
            bin_centers, (const int4*)idx, lb, ub, out, nchunks);
    }

    int done = nchunks * 128;
    if (done < n_rows) {
        int rem = n_rows - done;
        tail_kernel<<<(rem + 255) / 256, 256>>>(
            bin_centers, idx, lb, ub, out, done, n_rows);
    }
}